// round 6
// baseline (speedup 1.0000x reference)
#include <cuda_runtime.h>
#include <math.h>

#define NJ 7
#define DT_ 0.01f
#define GRAV_ 9.81f
#define TPB 64

__device__ __forceinline__ void cross3(const float* a, const float* b, float* o) {
    o[0] = a[1]*b[2] - a[2]*b[1];
    o[1] = a[2]*b[0] - a[0]*b[2];
    o[2] = a[0]*b[1] - a[1]*b[0];
}
__device__ __forceinline__ void mat3v(const float* A, const float* x, float* y) {
    y[0] = A[0]*x[0] + A[1]*x[1] + A[2]*x[2];
    y[1] = A[3]*x[0] + A[4]*x[1] + A[5]*x[2];
    y[2] = A[6]*x[0] + A[7]*x[1] + A[8]*x[2];
}
__device__ __forceinline__ void mat3tv(const float* A, const float* x, float* y) {
    y[0] = A[0]*x[0] + A[3]*x[1] + A[6]*x[2];
    y[1] = A[1]*x[0] + A[4]*x[1] + A[7]*x[2];
    y[2] = A[2]*x[0] + A[5]*x[1] + A[8]*x[2];
}
// out = Xup * in, Xup = [[A,0],[-A*S(p),A]]; in=(w;l): out = (A w ; A (l - p x w))
__device__ __forceinline__ void applyXup(const float* A, const float* p, const float* in, float* out) {
    float pxw[3];
    cross3(p, in, pxw);
    float t[3] = { in[3] - pxw[0], in[4] - pxw[1], in[5] - pxw[2] };
    mat3v(A, in, out);
    mat3v(A, t, out + 3);
}
// out = Xup^T * in, in=(n;f): out = (A^T n + p x (A^T f) ; A^T f)
__device__ __forceinline__ void applyXupT(const float* A, const float* p, const float* in, float* out) {
    float t[3], n[3], pxt[3];
    mat3tv(A, in + 3, t);
    mat3tv(A, in, n);
    cross3(p, t, pxt);
    out[0] = n[0] + pxt[0];
    out[1] = n[1] + pxt[1];
    out[2] = n[2] + pxt[2];
    out[3] = t[0]; out[4] = t[1]; out[5] = t[2];
}
// symmetric 3x3 (packed xx,xy,xz,yy,yz,zz) times vector
__device__ __forceinline__ void sym3v(const float* J, const float* x, float* y) {
    y[0] = J[0]*x[0] + J[1]*x[1] + J[2]*x[2];
    y[1] = J[1]*x[0] + J[3]*x[1] + J[4]*x[2];
    y[2] = J[2]*x[0] + J[4]*x[1] + J[5]*x[2];
}

// smem layout per joint: ax3, p3, E9, Ibar6(xx,xy,xz,yy,yz,zz), hb3, m1 = 25 floats
#define JSTRIDE 25
#define OFF_AX 0
#define OFF_P  3
#define OFF_E  6
#define OFF_IB 15
#define OFF_HB 21
#define OFF_M  24

__global__ void __launch_bounds__(TPB, 6)
panda_dyn_kernel(const float* __restrict__ x, const float* __restrict__ u,
                 const float* __restrict__ axes, const float* __restrict__ Rtree,
                 const float* __restrict__ ptree, const float* __restrict__ Isp,
                 float* __restrict__ out, int B)
{
    __shared__ float sJ[NJ * JSTRIDE];
    // per-thread joint transforms, conflict-free layout [63][TPB]
    __shared__ float sAm[NJ * 9][TPB];

    if (threadIdx.x < NJ) {
        int i = threadIdx.x;
        float* d = &sJ[i * JSTRIDE];
        d[OFF_AX + 0] = axes[3*i + 0];
        d[OFF_AX + 1] = axes[3*i + 1];
        d[OFF_AX + 2] = axes[3*i + 2];
        d[OFF_P + 0] = ptree[3*i + 0];
        d[OFF_P + 1] = ptree[3*i + 1];
        d[OFF_P + 2] = ptree[3*i + 2];
        #pragma unroll
        for (int k = 0; k < 9; k++) d[OFF_E + k] = Rtree[9*i + k];
        const float* Im = &Isp[36 * i];
        d[OFF_IB + 0] = Im[0];   // xx
        d[OFF_IB + 1] = Im[1];   // xy
        d[OFF_IB + 2] = Im[2];   // xz
        d[OFF_IB + 3] = Im[7];   // yy
        d[OFF_IB + 4] = Im[8];   // yz
        d[OFF_IB + 5] = Im[14];  // zz
        // top-right block = skew(hb)
        d[OFF_HB + 0] = Im[2*6 + 4];  // hx
        d[OFF_HB + 1] = Im[0*6 + 5];  // hy
        d[OFF_HB + 2] = Im[1*6 + 3];  // hz
        d[OFF_M] = Im[3*6 + 3];       // m
    }
    __syncthreads();

    int b = blockIdx.x * blockDim.x + threadIdx.x;
    if (b >= B) return;
    int tid = threadIdx.x;

    const float QL[NJ] = {-2.9671f, -1.8326f, -2.9671f, -3.1416f, -2.9671f, -0.0873f, -2.9671f};
    const float QU[NJ] = { 2.9671f,  1.8326f,  2.9671f,  0.0f,     2.9671f,  3.8223f,  2.9671f};

    float q[NJ], qd[NJ], bb[NJ];
#pragma unroll
    for (int i = 0; i < NJ; i++) {
        q[i]  = fminf(fmaxf(x[b * 14 + i], QL[i]), QU[i]);
        qd[i] = x[b * 14 + 7 + i];
        bb[i] = u[b * 7 + i];          // will become tau - h
    }

    // ---- joint transforms: A_i = R(q_i)^T * R_tree[i] -> per-thread shared ----
#pragma unroll
    for (int i = 0; i < NJ; i++) {
        const float* ax = &sJ[i*JSTRIDE + OFF_AX];
        const float* E  = &sJ[i*JSTRIDE + OFF_E];
        float s, c;
        __sincosf(q[i], &s, &c);
        float oc = 1.0f - c;
        float R[9];
        R[0] = c + oc * ax[0] * ax[0];
        R[1] = -s * ax[2] + oc * ax[0] * ax[1];
        R[2] =  s * ax[1] + oc * ax[0] * ax[2];
        R[3] =  s * ax[2] + oc * ax[1] * ax[0];
        R[4] = c + oc * ax[1] * ax[1];
        R[5] = -s * ax[0] + oc * ax[1] * ax[2];
        R[6] = -s * ax[1] + oc * ax[2] * ax[0];
        R[7] =  s * ax[0] + oc * ax[2] * ax[1];
        R[8] = c + oc * ax[2] * ax[2];
#pragma unroll
        for (int r = 0; r < 3; r++)
#pragma unroll
            for (int cc = 0; cc < 3; cc++)
                sAm[i*9 + 3*r + cc][tid] = R[r] * E[cc] + R[3 + r] * E[3 + cc] + R[6 + r] * E[6 + cc];
    }

    // ---- RNEA forward pass (qdd = 0) with structured inertias ----
    float fw[NJ][3], fv[NJ][3];
    float pv[6] = {0.f, 0.f, 0.f, 0.f, 0.f, 0.f};
    float pa[6] = {0.f, 0.f, 0.f, 0.f, 0.f, GRAV_};
#pragma unroll
    for (int i = 0; i < NJ; i++) {
        const float* ax = &sJ[i*JSTRIDE + OFF_AX];
        const float* p  = &sJ[i*JSTRIDE + OFF_P];
        const float* Ib = &sJ[i*JSTRIDE + OFF_IB];
        const float* hb = &sJ[i*JSTRIDE + OFF_HB];
        float m = sJ[i*JSTRIDE + OFF_M];
        float Am[9];
#pragma unroll
        for (int k = 0; k < 9; k++) Am[k] = sAm[i*9 + k][tid];
        float xv[6], xa[6];
        applyXup(Am, p, pv, xv);
        applyXup(Am, p, pa, xa);
        float wJ[3] = { ax[0]*qd[i], ax[1]*qd[i], ax[2]*qd[i] };
        float v6[6] = { xv[0]+wJ[0], xv[1]+wJ[1], xv[2]+wJ[2], xv[3], xv[4], xv[5] };
        float cw[3], cl[3];
        cross3(v6, wJ, cw);
        cross3(v6 + 3, wJ, cl);
        float a6[6] = { xa[0]+cw[0], xa[1]+cw[1], xa[2]+cw[2],
                        xa[3]+cl[0], xa[4]+cl[1], xa[5]+cl[2] };
        // I v = (Ib w + hb x l ; m l - hb x w)
        float Ivn[3], Ivf[3], t1[3], t2[3];
        sym3v(Ib, v6, Ivn);
        cross3(hb, v6 + 3, t1);
        cross3(hb, v6, t2);
#pragma unroll
        for (int k = 0; k < 3; k++) { Ivn[k] += t1[k]; Ivf[k] = m * v6[3+k] - t2[k]; }
        float Ian[3], Iaf[3];
        sym3v(Ib, a6, Ian);
        cross3(hb, a6 + 3, t1);
        cross3(hb, a6, t2);
#pragma unroll
        for (int k = 0; k < 3; k++) { Ian[k] += t1[k]; Iaf[k] = m * a6[3+k] - t2[k]; }
        // f = Ia + (w x Ivn + l x Ivf ; w x Ivf)
        float c1[3], c2[3], c3[3];
        cross3(v6, Ivn, c1);
        cross3(v6 + 3, Ivf, c2);
        cross3(v6, Ivf, c3);
#pragma unroll
        for (int k = 0; k < 3; k++) {
            fw[i][k] = Ian[k] + c1[k] + c2[k];
            fv[i][k] = Iaf[k] + c3[k];
        }
#pragma unroll
        for (int k = 0; k < 6; k++) { pv[k] = v6[k]; pa[k] = a6[k]; }
    }

    // ---- backward pass: bb = tau - h ----
#pragma unroll
    for (int i = NJ - 1; i >= 0; i--) {
        const float* ax = &sJ[i*JSTRIDE + OFF_AX];
        bb[i] -= ax[0]*fw[i][0] + ax[1]*fw[i][1] + ax[2]*fw[i][2];
        if (i > 0) {
            float Am[9];
#pragma unroll
            for (int k = 0; k < 9; k++) Am[k] = sAm[i*9 + k][tid];
            float f6[6] = { fw[i][0], fw[i][1], fw[i][2], fv[i][0], fv[i][1], fv[i][2] };
            float o6[6];
            applyXupT(Am, &sJ[i*JSTRIDE + OFF_P], f6, o6);
#pragma unroll
            for (int k = 0; k < 3; k++) { fw[i-1][k] += o6[k]; fv[i-1][k] += o6[3+k]; }
        }
    }

    // ---- CRBA with 10-parameter composite inertia {Jc sym6, hc3, mc} ----
    float Mm[NJ][NJ];   // lower triangle only
    float Jc[6], hc[3], mc;
    {
        const float* Ib = &sJ[(NJ-1)*JSTRIDE + OFF_IB];
        const float* hb = &sJ[(NJ-1)*JSTRIDE + OFF_HB];
#pragma unroll
        for (int k = 0; k < 6; k++) Jc[k] = Ib[k];
#pragma unroll
        for (int k = 0; k < 3; k++) hc[k] = hb[k];
        mc = sJ[(NJ-1)*JSTRIDE + OFF_M];
    }
#pragma unroll
    for (int i = NJ - 1; i >= 0; i--) {
        const float* ax = &sJ[i*JSTRIDE + OFF_AX];
        // F = Ic * (ax;0) = (Jc ax ; ax x hc)
        float F[6];
        sym3v(Jc, ax, F);
        cross3(ax, hc, F + 3);
        Mm[i][i] = ax[0]*F[0] + ax[1]*F[1] + ax[2]*F[2] + 1e-8f;
#pragma unroll
        for (int j = i - 1; j >= 0; j--) {
            float Am[9];
#pragma unroll
            for (int k = 0; k < 9; k++) Am[k] = sAm[(j+1)*9 + k][tid];
            float o6[6];
            applyXupT(Am, &sJ[(j+1)*JSTRIDE + OFF_P], F, o6);
#pragma unroll
            for (int r = 0; r < 6; r++) F[r] = o6[r];
            const float* aj = &sJ[j*JSTRIDE + OFF_AX];
            Mm[i][j] = aj[0]*F[0] + aj[1]*F[1] + aj[2]*F[2];
        }
        if (i > 0) {
            const float* p = &sJ[i*JSTRIDE + OFF_P];
            float Am[9];
#pragma unroll
            for (int k = 0; k < 9; k++) Am[k] = sAm[i*9 + k][tid];
            // h' = A^T hc ; J' = A^T Jc A ;
            // J_new = J' + 2(h'.p) I - p h'^T - h' p^T - mc p p^T + mc |p|^2 I
            float hp[3];
            mat3tv(Am, hc, hp);
            float T[9];
#pragma unroll
            for (int cc = 0; cc < 3; cc++) {
                T[0*3+cc] = Jc[0]*Am[0*3+cc] + Jc[1]*Am[1*3+cc] + Jc[2]*Am[2*3+cc];
                T[1*3+cc] = Jc[1]*Am[0*3+cc] + Jc[3]*Am[1*3+cc] + Jc[4]*Am[2*3+cc];
                T[2*3+cc] = Jc[2]*Am[0*3+cc] + Jc[4]*Am[1*3+cc] + Jc[5]*Am[2*3+cc];
            }
            float Jp[6];
            Jp[0] = Am[0]*T[0] + Am[3]*T[3] + Am[6]*T[6];
            Jp[1] = Am[0]*T[1] + Am[3]*T[4] + Am[6]*T[7];
            Jp[2] = Am[0]*T[2] + Am[3]*T[5] + Am[6]*T[8];
            Jp[3] = Am[1]*T[1] + Am[4]*T[4] + Am[7]*T[7];
            Jp[4] = Am[1]*T[2] + Am[4]*T[5] + Am[7]*T[8];
            Jp[5] = Am[2]*T[2] + Am[5]*T[5] + Am[8]*T[8];
            float hdp = hp[0]*p[0] + hp[1]*p[1] + hp[2]*p[2];
            float pp  = p[0]*p[0] + p[1]*p[1] + p[2]*p[2];
            float diag = 2.0f*hdp + mc*pp;
            const float* Ibp = &sJ[(i-1)*JSTRIDE + OFF_IB];
            const float* hbp = &sJ[(i-1)*JSTRIDE + OFF_HB];
            Jc[0] = Ibp[0] + Jp[0] + diag - 2.0f*p[0]*hp[0] - mc*p[0]*p[0];
            Jc[1] = Ibp[1] + Jp[1] - (p[0]*hp[1] + hp[0]*p[1]) - mc*p[0]*p[1];
            Jc[2] = Ibp[2] + Jp[2] - (p[0]*hp[2] + hp[0]*p[2]) - mc*p[0]*p[2];
            Jc[3] = Ibp[3] + Jp[3] + diag - 2.0f*p[1]*hp[1] - mc*p[1]*p[1];
            Jc[4] = Ibp[4] + Jp[4] - (p[1]*hp[2] + hp[1]*p[2]) - mc*p[1]*p[2];
            Jc[5] = Ibp[5] + Jp[5] + diag - 2.0f*p[2]*hp[2] - mc*p[2]*p[2];
            hc[0] = hbp[0] + hp[0] + mc*p[0];
            hc[1] = hbp[1] + hp[1] + mc*p[1];
            hc[2] = hbp[2] + hp[2] + mc*p[2];
            mc += sJ[(i-1)*JSTRIDE + OFF_M];
        }
    }

    // ---- symmetric GE on lower triangle: M qdd = bb ----
#pragma unroll
    for (int k = 0; k < NJ; k++) {
        float inv = __fdividef(1.0f, Mm[k][k]);
#pragma unroll
        for (int r = k + 1; r < NJ; r++) {
            float fkt = Mm[r][k] * inv;
#pragma unroll
            for (int c2 = k + 1; c2 <= r; c2++) Mm[r][c2] -= fkt * Mm[c2][k];
            bb[r] -= fkt * bb[k];
        }
    }
    float qdd[NJ];
#pragma unroll
    for (int k = NJ - 1; k >= 0; k--) {
        float t = bb[k];
#pragma unroll
        for (int c2 = k + 1; c2 < NJ; c2++) t -= Mm[c2][k] * qdd[c2];
        qdd[k] = __fdividef(t, Mm[k][k]);
    }

    // ---- integrate & write ----
#pragma unroll
    for (int k = 0; k < NJ; k++) {
        float qdn = qd[k] + DT_ * qdd[k];
        float qn  = q[k] + DT_ * qdn;
        out[b * 14 + k] = qn;
        out[b * 14 + 7 + k] = qdn;
    }
}

extern "C" void kernel_launch(void* const* d_in, const int* in_sizes, int n_in,
                              void* d_out, int out_size) {
    const float* x     = (const float*)d_in[0];
    const float* u     = (const float*)d_in[1];
    const float* axes  = (const float*)d_in[2];
    const float* Rtree = (const float*)d_in[3];
    const float* ptree = (const float*)d_in[4];
    const float* Isp   = (const float*)d_in[5];
    float* out = (float*)d_out;

    int B = in_sizes[0] / 14;
    int blocks = (B + TPB - 1) / TPB;
    panda_dyn_kernel<<<blocks, TPB>>>(x, u, axes, Rtree, ptree, Isp, out, B);
}

// round 7
// speedup vs baseline: 1.1744x; 1.1744x over previous
#include <cuda_runtime.h>
#include <math.h>

#define NJ 7
#define DT_ 0.01f
#define GRAV_ 9.81f
#define TPB 64

__device__ __forceinline__ void cross3(const float* a, const float* b, float* o) {
    o[0] = a[1]*b[2] - a[2]*b[1];
    o[1] = a[2]*b[0] - a[0]*b[2];
    o[2] = a[0]*b[1] - a[1]*b[0];
}
__device__ __forceinline__ void mat3v(const float* A, const float* x, float* y) {
    y[0] = A[0]*x[0] + A[1]*x[1] + A[2]*x[2];
    y[1] = A[3]*x[0] + A[4]*x[1] + A[5]*x[2];
    y[2] = A[6]*x[0] + A[7]*x[1] + A[8]*x[2];
}
__device__ __forceinline__ void mat3tv(const float* A, const float* x, float* y) {
    y[0] = A[0]*x[0] + A[3]*x[1] + A[6]*x[2];
    y[1] = A[1]*x[0] + A[4]*x[1] + A[7]*x[2];
    y[2] = A[2]*x[0] + A[5]*x[1] + A[8]*x[2];
}
// out = Xup * in, Xup = [[A,0],[-A*S(p),A]]; in=(w;l): out = (A w ; A (l - p x w))
__device__ __forceinline__ void applyXup(const float* A, const float* p, const float* in, float* out) {
    float pxw[3];
    cross3(p, in, pxw);
    float t[3] = { in[3] - pxw[0], in[4] - pxw[1], in[5] - pxw[2] };
    mat3v(A, in, out);
    mat3v(A, t, out + 3);
}
// out = Xup^T * in, in=(n;f): out = (A^T n + p x (A^T f) ; A^T f)
__device__ __forceinline__ void applyXupT(const float* A, const float* p, const float* in, float* out) {
    float t[3], n[3], pxt[3];
    mat3tv(A, in + 3, t);
    mat3tv(A, in, n);
    cross3(p, t, pxt);
    out[0] = n[0] + pxt[0];
    out[1] = n[1] + pxt[1];
    out[2] = n[2] + pxt[2];
    out[3] = t[0]; out[4] = t[1]; out[5] = t[2];
}
// symmetric 3x3 (packed xx,xy,xz,yy,yz,zz) times vector
__device__ __forceinline__ void sym3v(const float* J, const float* x, float* y) {
    y[0] = J[0]*x[0] + J[1]*x[1] + J[2]*x[2];
    y[1] = J[1]*x[0] + J[3]*x[1] + J[4]*x[2];
    y[2] = J[2]*x[0] + J[4]*x[1] + J[5]*x[2];
}

// smem layout per joint: ax3, p3, E9, Ibar6(xx,xy,xz,yy,yz,zz), hb3, m1 = 25 floats
#define JSTRIDE 25
#define OFF_AX 0
#define OFF_P  3
#define OFF_E  6
#define OFF_IB 15
#define OFF_HB 21
#define OFF_M  24

__global__ void __launch_bounds__(TPB, 5)
panda_dyn_kernel(const float* __restrict__ x, const float* __restrict__ u,
                 const float* __restrict__ axes, const float* __restrict__ Rtree,
                 const float* __restrict__ ptree, const float* __restrict__ Isp,
                 float* __restrict__ out, int B)
{
    __shared__ float sJ[NJ * JSTRIDE];

    // stage + structure-extract constants (one joint per thread, NJ threads)
    if (threadIdx.x < NJ) {
        int i = threadIdx.x;
        float* d = &sJ[i * JSTRIDE];
        d[OFF_AX + 0] = axes[3*i + 0];
        d[OFF_AX + 1] = axes[3*i + 1];
        d[OFF_AX + 2] = axes[3*i + 2];
        d[OFF_P + 0] = ptree[3*i + 0];
        d[OFF_P + 1] = ptree[3*i + 1];
        d[OFF_P + 2] = ptree[3*i + 2];
        #pragma unroll
        for (int k = 0; k < 9; k++) d[OFF_E + k] = Rtree[9*i + k];
        const float* Im = &Isp[36 * i];
        d[OFF_IB + 0] = Im[0];   // xx
        d[OFF_IB + 1] = Im[1];   // xy
        d[OFF_IB + 2] = Im[2];   // xz
        d[OFF_IB + 3] = Im[7];   // yy
        d[OFF_IB + 4] = Im[8];   // yz
        d[OFF_IB + 5] = Im[14];  // zz
        // top-right block = skew(hb): [[0,-hz,hy],[hz,0,-hx],[-hy,hx,0]] at cols 3..5
        d[OFF_HB + 0] = Im[2*6 + 4];  // hx
        d[OFF_HB + 1] = Im[0*6 + 5];  // hy
        d[OFF_HB + 2] = Im[1*6 + 3];  // hz
        d[OFF_M] = Im[3*6 + 3];       // m
    }
    __syncthreads();

    int b = blockIdx.x * blockDim.x + threadIdx.x;
    if (b >= B) return;

    const float QL[NJ] = {-2.9671f, -1.8326f, -2.9671f, -3.1416f, -2.9671f, -0.0873f, -2.9671f};
    const float QU[NJ] = { 2.9671f,  1.8326f,  2.9671f,  0.0f,     2.9671f,  3.8223f,  2.9671f};

    float q[NJ], qd[NJ], bb[NJ];
#pragma unroll
    for (int i = 0; i < NJ; i++) {
        q[i]  = fminf(fmaxf(x[b * 14 + i], QL[i]), QU[i]);
        qd[i] = x[b * 14 + 7 + i];
        bb[i] = u[b * 7 + i];          // will become tau - h
    }

    // ---- joint transforms: A_i = R(q_i)^T * R_tree[i] ----
    float A[NJ][9];
#pragma unroll
    for (int i = 0; i < NJ; i++) {
        const float* ax = &sJ[i*JSTRIDE + OFF_AX];
        const float* E  = &sJ[i*JSTRIDE + OFF_E];
        float s, c;
        __sincosf(q[i], &s, &c);
        float oc = 1.0f - c;
        float R[9];
        R[0] = c + oc * ax[0] * ax[0];
        R[1] = -s * ax[2] + oc * ax[0] * ax[1];
        R[2] =  s * ax[1] + oc * ax[0] * ax[2];
        R[3] =  s * ax[2] + oc * ax[1] * ax[0];
        R[4] = c + oc * ax[1] * ax[1];
        R[5] = -s * ax[0] + oc * ax[1] * ax[2];
        R[6] = -s * ax[1] + oc * ax[2] * ax[0];
        R[7] =  s * ax[0] + oc * ax[2] * ax[1];
        R[8] = c + oc * ax[2] * ax[2];
#pragma unroll
        for (int r = 0; r < 3; r++)
#pragma unroll
            for (int cc = 0; cc < 3; cc++)
                A[i][3*r + cc] = R[r] * E[cc] + R[3 + r] * E[3 + cc] + R[6 + r] * E[6 + cc];
    }

    // ---- RNEA forward pass (qdd = 0) with structured inertias ----
    float fw[NJ][3], fv[NJ][3];
    float pv[6] = {0.f, 0.f, 0.f, 0.f, 0.f, 0.f};
    float pa[6] = {0.f, 0.f, 0.f, 0.f, 0.f, GRAV_};
#pragma unroll
    for (int i = 0; i < NJ; i++) {
        const float* ax = &sJ[i*JSTRIDE + OFF_AX];
        const float* p  = &sJ[i*JSTRIDE + OFF_P];
        const float* Ib = &sJ[i*JSTRIDE + OFF_IB];
        const float* hb = &sJ[i*JSTRIDE + OFF_HB];
        float m = sJ[i*JSTRIDE + OFF_M];
        const float* Am = A[i];
        float xv[6], xa[6];
        applyXup(Am, p, pv, xv);
        applyXup(Am, p, pa, xa);
        float wJ[3] = { ax[0]*qd[i], ax[1]*qd[i], ax[2]*qd[i] };
        float v6[6] = { xv[0]+wJ[0], xv[1]+wJ[1], xv[2]+wJ[2], xv[3], xv[4], xv[5] };
        float cw[3], cl[3];
        cross3(v6, wJ, cw);
        cross3(v6 + 3, wJ, cl);
        float a6[6] = { xa[0]+cw[0], xa[1]+cw[1], xa[2]+cw[2],
                        xa[3]+cl[0], xa[4]+cl[1], xa[5]+cl[2] };
        // I v = (Ib w + hb x l ; m l - hb x w)
        float Ivn[3], Ivf[3], t1[3], t2[3];
        sym3v(Ib, v6, Ivn);
        cross3(hb, v6 + 3, t1);
        cross3(hb, v6, t2);
#pragma unroll
        for (int k = 0; k < 3; k++) { Ivn[k] += t1[k]; Ivf[k] = m * v6[3+k] - t2[k]; }
        float Ian[3], Iaf[3];
        sym3v(Ib, a6, Ian);
        cross3(hb, a6 + 3, t1);
        cross3(hb, a6, t2);
#pragma unroll
        for (int k = 0; k < 3; k++) { Ian[k] += t1[k]; Iaf[k] = m * a6[3+k] - t2[k]; }
        // f = Ia + (w x Ivn + l x Ivf ; w x Ivf)
        float c1[3], c2[3], c3[3];
        cross3(v6, Ivn, c1);
        cross3(v6 + 3, Ivf, c2);
        cross3(v6, Ivf, c3);
#pragma unroll
        for (int k = 0; k < 3; k++) {
            fw[i][k] = Ian[k] + c1[k] + c2[k];
            fv[i][k] = Iaf[k] + c3[k];
        }
#pragma unroll
        for (int k = 0; k < 6; k++) { pv[k] = v6[k]; pa[k] = a6[k]; }
    }

    // ---- backward pass: bb = tau - h ----
#pragma unroll
    for (int i = NJ - 1; i >= 0; i--) {
        const float* ax = &sJ[i*JSTRIDE + OFF_AX];
        bb[i] -= ax[0]*fw[i][0] + ax[1]*fw[i][1] + ax[2]*fw[i][2];
        if (i > 0) {
            float f6[6] = { fw[i][0], fw[i][1], fw[i][2], fv[i][0], fv[i][1], fv[i][2] };
            float o6[6];
            applyXupT(A[i], &sJ[i*JSTRIDE + OFF_P], f6, o6);
#pragma unroll
            for (int k = 0; k < 3; k++) { fw[i-1][k] += o6[k]; fv[i-1][k] += o6[3+k]; }
        }
    }

    // ---- CRBA with 10-parameter composite inertia {Jc sym6, hc3, mc} ----
    float Mm[NJ][NJ];   // lower triangle only
    float Jc[6], hc[3], mc;
    {
        const float* Ib = &sJ[(NJ-1)*JSTRIDE + OFF_IB];
        const float* hb = &sJ[(NJ-1)*JSTRIDE + OFF_HB];
#pragma unroll
        for (int k = 0; k < 6; k++) Jc[k] = Ib[k];
#pragma unroll
        for (int k = 0; k < 3; k++) hc[k] = hb[k];
        mc = sJ[(NJ-1)*JSTRIDE + OFF_M];
    }
#pragma unroll
    for (int i = NJ - 1; i >= 0; i--) {
        const float* ax = &sJ[i*JSTRIDE + OFF_AX];
        // F = Ic * (ax;0) = (Jc ax ; ax x hc)
        float F[6];
        sym3v(Jc, ax, F);
        cross3(ax, hc, F + 3);
        Mm[i][i] = ax[0]*F[0] + ax[1]*F[1] + ax[2]*F[2] + 1e-8f;
#pragma unroll
        for (int j = i - 1; j >= 0; j--) {
            float o6[6];
            applyXupT(A[j+1], &sJ[(j+1)*JSTRIDE + OFF_P], F, o6);
#pragma unroll
            for (int r = 0; r < 6; r++) F[r] = o6[r];
            const float* aj = &sJ[j*JSTRIDE + OFF_AX];
            Mm[i][j] = aj[0]*F[0] + aj[1]*F[1] + aj[2]*F[2];
        }
        if (i > 0) {
            const float* p  = &sJ[i*JSTRIDE + OFF_P];
            const float* Am = A[i];
            // transform composite into parent frame:
            // h' = A^T hc ; J' = A^T Jc A ;
            // J_new = J' + 2(h'.p) I - p h'^T - h' p^T - mc p p^T + mc |p|^2 I
            // h_new = h' + mc p ; m_new = mc
            float hp[3];
            mat3tv(Am, hc, hp);
            // T = Jc(sym) * A  (T[r][c] = sum_k Jc[r][k] A[k][c])
            float T[9];
#pragma unroll
            for (int cc = 0; cc < 3; cc++) {
                T[0*3+cc] = Jc[0]*Am[0*3+cc] + Jc[1]*Am[1*3+cc] + Jc[2]*Am[2*3+cc];
                T[1*3+cc] = Jc[1]*Am[0*3+cc] + Jc[3]*Am[1*3+cc] + Jc[4]*Am[2*3+cc];
                T[2*3+cc] = Jc[2]*Am[0*3+cc] + Jc[4]*Am[1*3+cc] + Jc[5]*Am[2*3+cc];
            }
            // Jp = A^T T, 6 uniques
            float Jp[6];
            Jp[0] = Am[0]*T[0] + Am[3]*T[3] + Am[6]*T[6];
            Jp[1] = Am[0]*T[1] + Am[3]*T[4] + Am[6]*T[7];
            Jp[2] = Am[0]*T[2] + Am[3]*T[5] + Am[6]*T[8];
            Jp[3] = Am[1]*T[1] + Am[4]*T[4] + Am[7]*T[7];
            Jp[4] = Am[1]*T[2] + Am[4]*T[5] + Am[7]*T[8];
            Jp[5] = Am[2]*T[2] + Am[5]*T[5] + Am[8]*T[8];
            float hdp = hp[0]*p[0] + hp[1]*p[1] + hp[2]*p[2];
            float pp  = p[0]*p[0] + p[1]*p[1] + p[2]*p[2];
            float diag = 2.0f*hdp + mc*pp;
            const float* Ibp = &sJ[(i-1)*JSTRIDE + OFF_IB];
            const float* hbp = &sJ[(i-1)*JSTRIDE + OFF_HB];
            Jc[0] = Ibp[0] + Jp[0] + diag - 2.0f*p[0]*hp[0] - mc*p[0]*p[0];
            Jc[1] = Ibp[1] + Jp[1] - (p[0]*hp[1] + hp[0]*p[1]) - mc*p[0]*p[1];
            Jc[2] = Ibp[2] + Jp[2] - (p[0]*hp[2] + hp[0]*p[2]) - mc*p[0]*p[2];
            Jc[3] = Ibp[3] + Jp[3] + diag - 2.0f*p[1]*hp[1] - mc*p[1]*p[1];
            Jc[4] = Ibp[4] + Jp[4] - (p[1]*hp[2] + hp[1]*p[2]) - mc*p[1]*p[2];
            Jc[5] = Ibp[5] + Jp[5] + diag - 2.0f*p[2]*hp[2] - mc*p[2]*p[2];
            hc[0] = hbp[0] + hp[0] + mc*p[0];
            hc[1] = hbp[1] + hp[1] + mc*p[1];
            hc[2] = hbp[2] + hp[2] + mc*p[2];
            mc += sJ[(i-1)*JSTRIDE + OFF_M];
        }
    }

    // ---- symmetric GE on lower triangle: M qdd = bb ----
#pragma unroll
    for (int k = 0; k < NJ; k++) {
        float inv = __fdividef(1.0f, Mm[k][k]);
#pragma unroll
        for (int r = k + 1; r < NJ; r++) {
            float fkt = Mm[r][k] * inv;
#pragma unroll
            for (int c2 = k + 1; c2 <= r; c2++) Mm[r][c2] -= fkt * Mm[c2][k];
            bb[r] -= fkt * bb[k];
        }
    }
    float qdd[NJ];
#pragma unroll
    for (int k = NJ - 1; k >= 0; k--) {
        float t = bb[k];
#pragma unroll
        for (int c2 = k + 1; c2 < NJ; c2++) t -= Mm[c2][k] * qdd[c2];
        qdd[k] = __fdividef(t, Mm[k][k]);
    }

    // ---- integrate & write ----
#pragma unroll
    for (int k = 0; k < NJ; k++) {
        float qdn = qd[k] + DT_ * qdd[k];
        float qn  = q[k] + DT_ * qdn;
        out[b * 14 + k] = qn;
        out[b * 14 + 7 + k] = qdn;
    }
}

extern "C" void kernel_launch(void* const* d_in, const int* in_sizes, int n_in,
                              void* d_out, int out_size) {
    const float* x     = (const float*)d_in[0];
    const float* u     = (const float*)d_in[1];
    const float* axes  = (const float*)d_in[2];
    const float* Rtree = (const float*)d_in[3];
    const float* ptree = (const float*)d_in[4];
    const float* Isp   = (const float*)d_in[5];
    float* out = (float*)d_out;

    int B = in_sizes[0] / 14;
    int blocks = (B + TPB - 1) / TPB;
    panda_dyn_kernel<<<blocks, TPB>>>(x, u, axes, Rtree, ptree, Isp, out, B);
}